// round 1
// baseline (speedup 1.0000x reference)
#include <cuda_runtime.h>
#include <math.h>

#define B_   4
#define C_   16
#define T_   32
#define HW_  4096
#define BC_  64
#define EPS_ 1e-10f
#define SCALE_ 0.8408964152537145f   // 2^-0.25

// ---------------- scratch (device globals; no allocation) ----------------
__device__ float g_qkvs[BC_][6][HW_];        // per (b,c): qs0,qs1,ks0,ks1,vs0,vs1
__device__ float g_qkvt[BC_][6][T_];         // per (b,c): qt0,qt1,kt0,kt1,vt0,vt1
__device__ float g_S   [B_][32][HW_];        // sqrt(qs'+eps), cd = c*2+d
__device__ float g_sqt [B_][32][T_];         // sqrt(qt'+eps)
__device__ float g_ctx [B_][C_][2][2];       // context[d][e]
__device__ float g_G   [B_][T_][2][32][16];  // [b][t][{s,t}][cd][c']

// ---------------- warp/block reduction helpers ----------------
__device__ __forceinline__ float warpSumAll(float v) {
#pragma unroll
    for (int o = 16; o > 0; o >>= 1) v += __shfl_xor_sync(0xffffffffu, v, o);
    return v;
}
__device__ __forceinline__ float warpMaxAll(float v) {
#pragma unroll
    for (int o = 16; o > 0; o >>= 1) v = fmaxf(v, __shfl_xor_sync(0xffffffffu, v, o));
    return v;
}
__device__ __forceinline__ float blockSum256(float v) {
    __shared__ float red[8];
    int lane = threadIdx.x & 31, wid = threadIdx.x >> 5;
    float s = warpSumAll(v);
    __syncthreads();
    if (lane == 0) red[wid] = s;
    __syncthreads();
    float r = red[0];
#pragma unroll
    for (int w = 1; w < 8; w++) r += red[w];
    return r;
}
__device__ __forceinline__ float blockMax256(float v) {
    __shared__ float redm[8];
    int lane = threadIdx.x & 31, wid = threadIdx.x >> 5;
    float s = warpMaxAll(v);
    __syncthreads();
    if (lane == 0) redm[wid] = s;
    __syncthreads();
    float r = redm[0];
#pragma unroll
    for (int w = 1; w < 8; w++) r = fmaxf(r, redm[w]);
    return r;
}

// ---------------- K1a: qkv_s[b,c,k,n] = sum_t x[b,c,t,n] * w_qkv_s[k,t] ----------------
// grid (64, 2): (bc, n-half of 2048). 256 threads, 8 cols/thread (4 at a time).
__global__ __launch_bounds__(256) void k1a(const float* __restrict__ x,
                                           const float* __restrict__ wqs) {
    int bc = blockIdx.x;
    int noff = blockIdx.y * 2048;
    int j = threadIdx.x;
    const float* xs = x + (size_t)bc * T_ * HW_;
    __shared__ float ws_sh[192];   // [k][t] = k*32+t
    if (j < 192) ws_sh[j] = wqs[j];
    __syncthreads();

    for (int i = 0; i < 2; i++) {
        int n0 = noff + i * 1024 + j;   // cols n0, n0+256, n0+512, n0+768
        float acc[6][4];
#pragma unroll
        for (int k = 0; k < 6; k++)
#pragma unroll
            for (int m = 0; m < 4; m++) acc[k][m] = 0.f;
#pragma unroll
        for (int t = 0; t < T_; t++) {
            float v0 = xs[t * HW_ + n0];
            float v1 = xs[t * HW_ + n0 + 256];
            float v2 = xs[t * HW_ + n0 + 512];
            float v3 = xs[t * HW_ + n0 + 768];
#pragma unroll
            for (int k = 0; k < 6; k++) {
                float w = ws_sh[k * 32 + t];
                acc[k][0] += v0 * w; acc[k][1] += v1 * w;
                acc[k][2] += v2 * w; acc[k][3] += v3 * w;
            }
        }
#pragma unroll
        for (int k = 0; k < 6; k++)
#pragma unroll
            for (int m = 0; m < 4; m++)
                g_qkvs[bc][k][n0 + m * 256] = acc[k][m];
    }
}

// ---------------- K1b: qkv_t[b,c,k,t] = sum_n x[b,c,t,n] * w_qkv_t[k,n] ----------------
// grid (64, 2): (bc, t-half of 16). 256 threads; register tile acc[6][16]; deterministic reduce.
__global__ __launch_bounds__(256) void k1b(const float* __restrict__ x,
                                           const float* __restrict__ wqt) {
    int bc = blockIdx.x;
    int t0 = blockIdx.y * 16;
    int j = threadIdx.x;
    const float* xs = x + (size_t)bc * T_ * HW_ + (size_t)t0 * HW_;

    float acc[6][16];
#pragma unroll
    for (int k = 0; k < 6; k++)
#pragma unroll
        for (int tt = 0; tt < 16; tt++) acc[k][tt] = 0.f;

    for (int i = 0; i < 16; i++) {
        int n = i * 256 + j;
        float wv[6];
#pragma unroll
        for (int k = 0; k < 6; k++) wv[k] = wqt[k * HW_ + n];
#pragma unroll
        for (int tt = 0; tt < 16; tt++) {
            float v = xs[tt * HW_ + n];
#pragma unroll
            for (int k = 0; k < 6; k++) acc[k][tt] += v * wv[k];
        }
    }

    __shared__ float wpart[8][96];
    int lane = j & 31, wid = j >> 5;
#pragma unroll
    for (int k = 0; k < 6; k++)
#pragma unroll
        for (int tt = 0; tt < 16; tt++) {
            float v = warpSumAll(acc[k][tt]);
            if (lane == 0) wpart[wid][k * 16 + tt] = v;
        }
    __syncthreads();
    if (j < 96) {
        float s = 0.f;
#pragma unroll
        for (int w = 0; w < 8; w++) s += wpart[w][j];
        int k = j >> 4, tt = j & 15;
        g_qkvt[bc][k][t0 + tt] = s;
    }
}

// ---------------- K2: softmaxes, context factors, S ----------------
// grid (64): one block per (b,c), 256 threads.
__global__ __launch_bounds__(256) void k2() {
    int bc = blockIdx.x;
    int b = bc >> 4, c = bc & 15;
    const float* qv = &g_qkvs[bc][0][0];
    int tid = threadIdx.x;

    __shared__ float qt_sh[192];
    __shared__ float ct_sh[4];
    __shared__ float stat[4];   // M0, 1/Z0, M1, 1/Z1 for ks
    if (tid < 192) qt_sh[tid] = (&g_qkvt[bc][0][0])[tid];
    __syncthreads();

    if (tid < 32) {
        int t = tid;
        // qt softmax over d (pairwise), store sqrt(qt'+eps)
        float q0 = qt_sh[t], q1 = qt_sh[32 + t];
        float m = fmaxf(q0, q1);
        float e0 = expf(q0 - m), e1 = expf(q1 - m);
        float inv = 1.f / (e0 + e1);
        g_sqt[b][2 * c][t]     = sqrtf(e0 * inv + EPS_);
        g_sqt[b][2 * c + 1][t] = sqrtf(e1 * inv + EPS_);
        // kt softmax over t per d
        float k0 = qt_sh[64 + t], k1 = qt_sh[96 + t];
        float M0 = warpMaxAll(k0), M1 = warpMaxAll(k1);
        float x0 = expf(k0 - M0), x1 = expf(k1 - M1);
        float Z0 = warpSumAll(x0), Z1 = warpSumAll(x1);
        float kt0 = x0 / Z0 + EPS_, kt1 = x1 / Z1 + EPS_;
        float vt0 = qt_sh[128 + t], vt1 = qt_sh[160 + t];
        float c00 = warpSumAll(sqrtf(kt0 * vt0));
        float c01 = warpSumAll(sqrtf(kt0 * vt1));
        float c10 = warpSumAll(sqrtf(kt1 * vt0));
        float c11 = warpSumAll(sqrtf(kt1 * vt1));
        if (t == 0) { ct_sh[0] = c00; ct_sh[1] = c01; ct_sh[2] = c10; ct_sh[3] = c11; }
    }

    // ks softmax stats over n (per d)
    for (int d = 0; d < 2; d++) {
        const float* row = qv + (2 + d) * HW_;
        float m = -1e30f;
        for (int n = tid; n < HW_; n += 256) m = fmaxf(m, row[n]);
        m = blockMax256(m);
        float s = 0.f;
        for (int n = tid; n < HW_; n += 256) s += expf(row[n] - m);
        s = blockSum256(s);
        if (tid == 0) { stat[2 * d] = m; stat[2 * d + 1] = 1.f / s; }
        __syncthreads();
    }
    float M0 = stat[0], iZ0 = stat[1], M1 = stat[2], iZ1 = stat[3];

    // Cn[d][e] = sum_n sqrt(ks'[d,n] * vs[e,n])
    float cn00 = 0, cn01 = 0, cn10 = 0, cn11 = 0;
    for (int n = tid; n < HW_; n += 256) {
        float p0 = expf(qv[2 * HW_ + n] - M0) * iZ0 + EPS_;
        float p1 = expf(qv[3 * HW_ + n] - M1) * iZ1 + EPS_;
        float v0 = qv[4 * HW_ + n], v1 = qv[5 * HW_ + n];
        cn00 += sqrtf(p0 * v0); cn01 += sqrtf(p0 * v1);
        cn10 += sqrtf(p1 * v0); cn11 += sqrtf(p1 * v1);
    }
    cn00 = blockSum256(cn00); cn01 = blockSum256(cn01);
    cn10 = blockSum256(cn10); cn11 = blockSum256(cn11);

    // S = sqrt(softmax_d(qs) + eps)
    for (int n = tid; n < HW_; n += 256) {
        float a = qv[n], bb = qv[HW_ + n];
        float m = fmaxf(a, bb);
        float e0 = expf(a - m), e1 = expf(bb - m);
        float inv = 1.f / (e0 + e1);
        g_S[b][2 * c][n]     = sqrtf(e0 * inv + EPS_);
        g_S[b][2 * c + 1][n] = sqrtf(e1 * inv + EPS_);
    }

    if (tid == 0) {
        g_ctx[b][c][0][0] = SCALE_ * ct_sh[0] * cn00;
        g_ctx[b][c][0][1] = SCALE_ * ct_sh[1] * cn01;
        g_ctx[b][c][1][0] = SCALE_ * ct_sh[2] * cn10;
        g_ctx[b][c][1][1] = SCALE_ * ct_sh[3] * cn11;
    }
}

// ---------------- K2b: build G[b][t][{s,t}][cd][c'] ----------------
__global__ void k2b(const float* __restrict__ wos, const float* __restrict__ wot) {
    int b = blockIdx.x;
    for (int idx = threadIdx.x; idx < T_ * 32 * 16; idx += blockDim.x) {
        int t = idx >> 9; int r = idx & 511; int cd = r >> 4; int cp = r & 15;
        int c = cd >> 1, d = cd & 1;
        float x0 = g_ctx[b][c][d][0], x1 = g_ctx[b][c][d][1];
        float As = wos[cp * 32 + 2 * c] * x0 + wos[cp * 32 + 2 * c + 1] * x1;
        float At = wot[cp * 32 + 2 * c] * x0 + wot[cp * 32 + 2 * c + 1] * x1;
        float sq = SCALE_ * g_sqt[b][cd][t];
        g_G[b][t][0][cd][cp] = As * sq;
        g_G[b][t][1][cd][cp] = At * sq;
    }
}

// ---------------- K3: out[c',t,n] = sqrt( (G_s[.,t]·S)[c',n] * (G_t[.,t]·S)[c',n] ) ----------------
// grid 2048 = b(4) * t(32) * ntile(16 of 256). 256 threads; thread tile 4 c' x 4 n.
__global__ __launch_bounds__(256) void k3(float* __restrict__ out) {
    int bid = blockIdx.x;
    int b = bid >> 9; int rem = bid & 511; int t = rem >> 4; int nb = rem & 15;
    int n0 = nb * 256;
    __shared__ float Ssh[32 * 256];
    __shared__ float Gsh[1024];     // [0..511] = G_s[cd][cp], [512..1023] = G_t[cd][cp]
    int j = threadIdx.x;

    ((float4*)Gsh)[j] = ((const float4*)&g_G[b][t][0][0][0])[j];
    for (int idx = j; idx < 32 * 64; idx += 256) {
        int r = idx >> 6, q4 = idx & 63;
        ((float4*)Ssh)[r * 64 + q4] = ((const float4*)(&g_S[b][r][n0]))[q4];
    }
    __syncthreads();

    int cg = j >> 6, ng = j & 63;
    float as[4][4], at[4][4];
#pragma unroll
    for (int p = 0; p < 4; p++)
#pragma unroll
        for (int m = 0; m < 4; m++) { as[p][m] = 0.f; at[p][m] = 0.f; }

    const float* Gs = Gsh;
    const float* Gt = Gsh + 512;
#pragma unroll 4
    for (int cd = 0; cd < 32; cd++) {
        float4 sv = ((const float4*)Ssh)[cd * 64 + ng];
#pragma unroll
        for (int p = 0; p < 4; p++) {
            float gsv = Gs[cd * 16 + cg * 4 + p];
            float gtv = Gt[cd * 16 + cg * 4 + p];
            as[p][0] += gsv * sv.x; as[p][1] += gsv * sv.y;
            as[p][2] += gsv * sv.z; as[p][3] += gsv * sv.w;
            at[p][0] += gtv * sv.x; at[p][1] += gtv * sv.y;
            at[p][2] += gtv * sv.z; at[p][3] += gtv * sv.w;
        }
    }

#pragma unroll
    for (int p = 0; p < 4; p++) {
        int cp = cg * 4 + p;
        float4 o;
        o.x = sqrtf(as[p][0] * at[p][0]);
        o.y = sqrtf(as[p][1] * at[p][1]);
        o.z = sqrtf(as[p][2] * at[p][2]);
        o.w = sqrtf(as[p][3] * at[p][3]);
        *(float4*)&out[(((size_t)(b * 16 + cp) * 32 + t) * HW_) + n0 + ng * 4] = o;
    }
}

// ---------------- launch ----------------
extern "C" void kernel_launch(void* const* d_in, const int* in_sizes, int n_in,
                              void* d_out, int out_size) {
    const float* x   = (const float*)d_in[0];
    const float* wqs = (const float*)d_in[1];
    const float* wqt = (const float*)d_in[2];
    const float* wos = (const float*)d_in[3];
    const float* wot = (const float*)d_in[4];
    float* out = (float*)d_out;

    k1a<<<dim3(BC_, 2), 256>>>(x, wqs);
    k1b<<<dim3(BC_, 2), 256>>>(x, wqt);
    k2 <<<BC_, 256>>>();
    k2b<<<B_, 512>>>(wos, wot);
    k3 <<<B_ * T_ * 16, 256>>>(out);
}

// round 2
// speedup vs baseline: 1.3348x; 1.3348x over previous
#include <cuda_runtime.h>
#include <math.h>

#define B_   4
#define C_   16
#define T_   32
#define HW_  4096
#define BC_  64
#define EPS_ 1e-10f
#define SCALE_ 0.8408964152537145f   // 2^-0.25

// ---------------- scratch (device globals; no allocation) ----------------
__device__ float g_qkvs[BC_][6][HW_];        // per (b,c): qs0,qs1,ks0,ks1,vs0,vs1
__device__ float g_qkvt[BC_][6][T_];         // per (b,c): qt0,qt1,kt0,kt1,vt0,vt1
__device__ float g_S   [B_][32][HW_];        // sqrt(qs'+eps), cd = c*2+d
__device__ float g_sqt [B_][32][T_];         // SCALE * sqrt(qt'+eps)
__device__ float g_A   [B_][2][32][16];      // [b][{s,t}][cd][c']  (t-independent factor)

// ---------------- helpers ----------------
__device__ __forceinline__ float warpSumAll(float v) {
#pragma unroll
    for (int o = 16; o > 0; o >>= 1) v += __shfl_xor_sync(0xffffffffu, v, o);
    return v;
}
__device__ __forceinline__ float warpMaxAll(float v) {
#pragma unroll
    for (int o = 16; o > 0; o >>= 1) v = fmaxf(v, __shfl_xor_sync(0xffffffffu, v, o));
    return v;
}
__device__ __forceinline__ float blockSum256(float v) {
    __shared__ float red[8];
    int lane = threadIdx.x & 31, wid = threadIdx.x >> 5;
    float s = warpSumAll(v);
    __syncthreads();
    if (lane == 0) red[wid] = s;
    __syncthreads();
    float r = red[0];
#pragma unroll
    for (int w = 1; w < 8; w++) r += red[w];
    return r;
}
__device__ __forceinline__ float blockMax256(float v) {
    __shared__ float redm[8];
    int lane = threadIdx.x & 31, wid = threadIdx.x >> 5;
    float s = warpMaxAll(v);
    __syncthreads();
    if (lane == 0) redm[wid] = s;
    __syncthreads();
    float r = redm[0];
#pragma unroll
    for (int w = 1; w < 8; w++) r = fmaxf(r, redm[w]);
    return r;
}

__device__ __forceinline__ unsigned long long pack2(float lo, float hi) {
    unsigned long long r;
    asm("mov.b64 %0, {%1, %2};" : "=l"(r) : "f"(lo), "f"(hi));
    return r;
}
__device__ __forceinline__ unsigned long long fma2(unsigned long long a,
                                                   unsigned long long b,
                                                   unsigned long long c) {
    unsigned long long d;
    asm("fma.rn.f32x2 %0, %1, %2, %3;" : "=l"(d) : "l"(a), "l"(b), "l"(c));
    return d;
}
__device__ __forceinline__ float2 unpk2(unsigned long long v) {
    float2 f;
    asm("mov.b64 {%0, %1}, %2;" : "=f"(f.x), "=f"(f.y) : "l"(v));
    return f;
}
__device__ __forceinline__ float sqrt_ap(float x) {
    float r;
    asm("sqrt.approx.f32 %0, %1;" : "=f"(r) : "f"(x));
    return r;
}

// ---------------- K1a: qkv_s[b,c,k,n] = sum_t x[b,c,t,n] * w_qkv_s[k,t] ----------------
__global__ __launch_bounds__(256) void k1a(const float* __restrict__ x,
                                           const float* __restrict__ wqs) {
    int bc = blockIdx.x;
    int noff = blockIdx.y * 2048;
    int j = threadIdx.x;
    const float* xs = x + (size_t)bc * T_ * HW_;
    __shared__ float ws_sh[192];
    if (j < 192) ws_sh[j] = wqs[j];
    __syncthreads();

    for (int i = 0; i < 2; i++) {
        int n0 = noff + i * 1024 + j;
        float acc[6][4];
#pragma unroll
        for (int k = 0; k < 6; k++)
#pragma unroll
            for (int m = 0; m < 4; m++) acc[k][m] = 0.f;
#pragma unroll
        for (int t = 0; t < T_; t++) {
            float v0 = xs[t * HW_ + n0];
            float v1 = xs[t * HW_ + n0 + 256];
            float v2 = xs[t * HW_ + n0 + 512];
            float v3 = xs[t * HW_ + n0 + 768];
#pragma unroll
            for (int k = 0; k < 6; k++) {
                float w = ws_sh[k * 32 + t];
                acc[k][0] += v0 * w; acc[k][1] += v1 * w;
                acc[k][2] += v2 * w; acc[k][3] += v3 * w;
            }
        }
#pragma unroll
        for (int k = 0; k < 6; k++)
#pragma unroll
            for (int m = 0; m < 4; m++)
                g_qkvs[bc][k][n0 + m * 256] = acc[k][m];
    }
}

// ---------------- K1b: qkv_t[b,c,k,t] = sum_n x[b,c,t,n] * w_qkv_t[k,n] ----------------
__global__ __launch_bounds__(256) void k1b(const float* __restrict__ x,
                                           const float* __restrict__ wqt) {
    int bc = blockIdx.x;
    int t0 = blockIdx.y * 16;
    int j = threadIdx.x;
    const float* xs = x + (size_t)bc * T_ * HW_ + (size_t)t0 * HW_;

    float acc[6][16];
#pragma unroll
    for (int k = 0; k < 6; k++)
#pragma unroll
        for (int tt = 0; tt < 16; tt++) acc[k][tt] = 0.f;

    for (int i = 0; i < 16; i++) {
        int n = i * 256 + j;
        float wv[6];
#pragma unroll
        for (int k = 0; k < 6; k++) wv[k] = wqt[k * HW_ + n];
#pragma unroll
        for (int tt = 0; tt < 16; tt++) {
            float v = xs[tt * HW_ + n];
#pragma unroll
            for (int k = 0; k < 6; k++) acc[k][tt] += v * wv[k];
        }
    }

    __shared__ float wpart[8][96];
    int lane = j & 31, wid = j >> 5;
#pragma unroll
    for (int k = 0; k < 6; k++)
#pragma unroll
        for (int tt = 0; tt < 16; tt++) {
            float v = warpSumAll(acc[k][tt]);
            if (lane == 0) wpart[wid][k * 16 + tt] = v;
        }
    __syncthreads();
    if (j < 96) {
        float s = 0.f;
#pragma unroll
        for (int w = 0; w < 8; w++) s += wpart[w][j];
        int k = j >> 4, tt = j & 15;
        g_qkvt[bc][k][t0 + tt] = s;
    }
}

// ---------------- K2: softmaxes, context, S, sqt, and A = w_out x ctx ----------------
__global__ __launch_bounds__(256) void k2(const float* __restrict__ wos,
                                          const float* __restrict__ wot) {
    int bc = blockIdx.x;
    int b = bc >> 4, c = bc & 15;
    const float* qv = &g_qkvs[bc][0][0];
    int tid = threadIdx.x;

    __shared__ float qt_sh[192];
    __shared__ float ct_sh[4];
    __shared__ float stat[4];
    if (tid < 192) qt_sh[tid] = (&g_qkvt[bc][0][0])[tid];
    __syncthreads();

    if (tid < 32) {
        int t = tid;
        // qt softmax over d, store SCALE*sqrt(qt'+eps)
        float q0 = qt_sh[t], q1 = qt_sh[32 + t];
        float m = fmaxf(q0, q1);
        float e0 = __expf(q0 - m), e1 = __expf(q1 - m);
        float inv = 1.f / (e0 + e1);
        g_sqt[b][2 * c][t]     = SCALE_ * sqrtf(e0 * inv + EPS_);
        g_sqt[b][2 * c + 1][t] = SCALE_ * sqrtf(e1 * inv + EPS_);
        // kt softmax over t per d
        float k0 = qt_sh[64 + t], k1 = qt_sh[96 + t];
        float M0 = warpMaxAll(k0), M1 = warpMaxAll(k1);
        float x0 = __expf(k0 - M0), x1 = __expf(k1 - M1);
        float Z0 = warpSumAll(x0), Z1 = warpSumAll(x1);
        float kt0 = x0 / Z0 + EPS_, kt1 = x1 / Z1 + EPS_;
        float vt0 = qt_sh[128 + t], vt1 = qt_sh[160 + t];
        float c00 = warpSumAll(sqrtf(kt0 * vt0));
        float c01 = warpSumAll(sqrtf(kt0 * vt1));
        float c10 = warpSumAll(sqrtf(kt1 * vt0));
        float c11 = warpSumAll(sqrtf(kt1 * vt1));
        if (t == 0) { ct_sh[0] = c00; ct_sh[1] = c01; ct_sh[2] = c10; ct_sh[3] = c11; }
    }

    // ks softmax stats over n (per d)
    for (int d = 0; d < 2; d++) {
        const float* row = qv + (2 + d) * HW_;
        float m = -1e30f;
        for (int n = tid; n < HW_; n += 256) m = fmaxf(m, row[n]);
        m = blockMax256(m);
        float s = 0.f;
        for (int n = tid; n < HW_; n += 256) s += __expf(row[n] - m);
        s = blockSum256(s);
        if (tid == 0) { stat[2 * d] = m; stat[2 * d + 1] = 1.f / s; }
        __syncthreads();
    }
    float M0 = stat[0], iZ0 = stat[1], M1 = stat[2], iZ1 = stat[3];

    // Cn[d][e] = sum_n sqrt(ks'[d,n] * vs[e,n])
    float cn00 = 0, cn01 = 0, cn10 = 0, cn11 = 0;
    for (int n = tid; n < HW_; n += 256) {
        float p0 = __expf(qv[2 * HW_ + n] - M0) * iZ0 + EPS_;
        float p1 = __expf(qv[3 * HW_ + n] - M1) * iZ1 + EPS_;
        float v0 = qv[4 * HW_ + n], v1 = qv[5 * HW_ + n];
        cn00 += sqrtf(p0 * v0); cn01 += sqrtf(p0 * v1);
        cn10 += sqrtf(p1 * v0); cn11 += sqrtf(p1 * v1);
    }
    cn00 = blockSum256(cn00); cn01 = blockSum256(cn01);
    cn10 = blockSum256(cn10); cn11 = blockSum256(cn11);

    // S = sqrt(softmax_d(qs) + eps)
    for (int n = tid; n < HW_; n += 256) {
        float a = qv[n], bb = qv[HW_ + n];
        float m = fmaxf(a, bb);
        float e0 = __expf(a - m), e1 = __expf(bb - m);
        float inv = 1.f / (e0 + e1);
        g_S[b][2 * c][n]     = sqrtf(e0 * inv + EPS_);
        g_S[b][2 * c + 1][n] = sqrtf(e1 * inv + EPS_);
    }

    // A[b][st][2c+d][cp] = sum_e w[cp][2c+e] * (SCALE * ct[d][e] * cn[d][e])
    // (ct_sh already visible: blockSum256 above contains __syncthreads)
    if (tid < 64) {
        int cp = tid & 15, d = (tid >> 4) & 1, st = tid >> 5;
        float cne0 = d ? cn10 : cn00;
        float cne1 = d ? cn11 : cn01;
        float x0 = SCALE_ * ct_sh[2 * d]     * cne0;
        float x1 = SCALE_ * ct_sh[2 * d + 1] * cne1;
        const float* w = st ? wot : wos;
        g_A[b][st][2 * c + d][cp] = w[cp * 32 + 2 * c] * x0 + w[cp * 32 + 2 * c + 1] * x1;
    }
}

// ---------------- K3: out[c',t,n] = sqrt( (Gs·S) * (Gt·S) ), G = A * sqt[t] ----------------
// grid (16 ntiles of 256, 4 b, 2 tchunks of 16). 256 threads.
// thread tile: 4 c' (two f32x2 pairs) x 4 n, for both s and t branches.
__global__ __launch_bounds__(256) void k3(float* __restrict__ out) {
    int nt = blockIdx.x;        // 0..15
    int b  = blockIdx.y;        // 0..3
    int tc = blockIdx.z;        // 0..1
    int n0 = nt * 256;
    int j = threadIdx.x;

    __shared__ float Ssh[32][256];                       // 32 KB
    __shared__ float sqt_sh[32][16];                     // 2 KB
    __shared__ __align__(16) float Gsh[2][32][16];       // 4 KB, rebuilt per t

    // A tile in registers: thread j owns floats [4j..4j+3] of g_A[b] (1024 floats)
    float4 myA = ((const float4*)&g_A[b][0][0][0])[j];
    int myCd = (j >> 2) & 31;

    // load S tile
#pragma unroll
    for (int u = 0; u < 8; u++) {
        int idx = u * 256 + j;          // 0..2047 float4s
        int r = idx >> 6, q = idx & 63;
        ((float4*)&Ssh[r][0])[q] = ((const float4*)&g_S[b][r][n0])[q];
    }
    // load sqt chunk (already includes SCALE)
    if (j < 128) {
        int cd = j >> 2, q = j & 3;
        ((float4*)&sqt_sh[cd][0])[q] = *(const float4*)&g_sqt[b][cd][tc * 16 + q * 4];
    }
    __syncthreads();

    int cg = j >> 6, ng = j & 63;
    int cpb = cg * 4;

    for (int tt = 0; tt < 16; tt++) {
        // rebuild G = A * (SCALE*sqt[t]) — each thread writes its own float4
        float sq = sqt_sh[myCd][tt];
        float4 g4;
        g4.x = myA.x * sq; g4.y = myA.y * sq; g4.z = myA.z * sq; g4.w = myA.w * sq;
        ((float4*)&Gsh[0][0][0])[j] = g4;
        __syncthreads();

        unsigned long long aS[2][4], aT[2][4];
#pragma unroll
        for (int p = 0; p < 2; p++)
#pragma unroll
            for (int m = 0; m < 4; m++) { aS[p][m] = 0ull; aT[p][m] = 0ull; }

#pragma unroll 4
        for (int cd = 0; cd < 32; cd++) {
            float4 sv = ((const float4*)&Ssh[cd][0])[ng];
            unsigned long long s0 = pack2(sv.x, sv.x);
            unsigned long long s1 = pack2(sv.y, sv.y);
            unsigned long long s2 = pack2(sv.z, sv.z);
            unsigned long long s3 = pack2(sv.w, sv.w);
            ulonglong2 gs = *(const ulonglong2*)&Gsh[0][cd][cpb];
            ulonglong2 gt = *(const ulonglong2*)&Gsh[1][cd][cpb];
            aS[0][0] = fma2(gs.x, s0, aS[0][0]);
            aS[0][1] = fma2(gs.x, s1, aS[0][1]);
            aS[0][2] = fma2(gs.x, s2, aS[0][2]);
            aS[0][3] = fma2(gs.x, s3, aS[0][3]);
            aS[1][0] = fma2(gs.y, s0, aS[1][0]);
            aS[1][1] = fma2(gs.y, s1, aS[1][1]);
            aS[1][2] = fma2(gs.y, s2, aS[1][2]);
            aS[1][3] = fma2(gs.y, s3, aS[1][3]);
            aT[0][0] = fma2(gt.x, s0, aT[0][0]);
            aT[0][1] = fma2(gt.x, s1, aT[0][1]);
            aT[0][2] = fma2(gt.x, s2, aT[0][2]);
            aT[0][3] = fma2(gt.x, s3, aT[0][3]);
            aT[1][0] = fma2(gt.y, s0, aT[1][0]);
            aT[1][1] = fma2(gt.y, s1, aT[1][1]);
            aT[1][2] = fma2(gt.y, s2, aT[1][2]);
            aT[1][3] = fma2(gt.y, s3, aT[1][3]);
        }

        int t = tc * 16 + tt;
#pragma unroll
        for (int p = 0; p < 2; p++) {
            float2 s0 = unpk2(aS[p][0]), s1 = unpk2(aS[p][1]);
            float2 s2 = unpk2(aS[p][2]), s3 = unpk2(aS[p][3]);
            float2 t0 = unpk2(aT[p][0]), t1 = unpk2(aT[p][1]);
            float2 t2 = unpk2(aT[p][2]), t3 = unpk2(aT[p][3]);
            size_t base = (((size_t)(b * 16 + cpb + 2 * p) * 32 + t) * HW_) + n0 + ng * 4;
            float4 o;
            o.x = sqrt_ap(s0.x * t0.x); o.y = sqrt_ap(s1.x * t1.x);
            o.z = sqrt_ap(s2.x * t2.x); o.w = sqrt_ap(s3.x * t3.x);
            *(float4*)&out[base] = o;
            float4 o2;
            o2.x = sqrt_ap(s0.y * t0.y); o2.y = sqrt_ap(s1.y * t1.y);
            o2.z = sqrt_ap(s2.y * t2.y); o2.w = sqrt_ap(s3.y * t3.y);
            *(float4*)&out[base + (size_t)T_ * HW_] = o2;
        }
        __syncthreads();   // Gsh reused next iteration
    }
}

// ---------------- launch ----------------
extern "C" void kernel_launch(void* const* d_in, const int* in_sizes, int n_in,
                              void* d_out, int out_size) {
    const float* x   = (const float*)d_in[0];
    const float* wqs = (const float*)d_in[1];
    const float* wqt = (const float*)d_in[2];
    const float* wos = (const float*)d_in[3];
    const float* wot = (const float*)d_in[4];
    float* out = (float*)d_out;

    k1a<<<dim3(BC_, 2), 256>>>(x, wqs);
    k1b<<<dim3(BC_, 2), 256>>>(x, wqt);
    k2 <<<BC_, 256>>>(wos, wot);
    k3 <<<dim3(16, B_, 2), 256>>>(out);
}

// round 3
// speedup vs baseline: 1.6088x; 1.2052x over previous
#include <cuda_runtime.h>
#include <math.h>

#define B_   4
#define C_   16
#define T_   32
#define HW_  4096
#define BC_  64
#define EPS_ 1e-10f
#define SCALE_ 0.8408964152537145f   // 2^-0.25

// ---------------- scratch (device globals) ----------------
__device__ float  g_S   [B_][32][HW_];     // sqrt(softmax_d(qs)+eps), row cd=2c+d
__device__ float  g_kv  [BC_][4][HW_];     // ks0,ks1,vs0,vs1 (raw)
__device__ float2 g_stat[BC_][4][2];       // per (bc, chunk, d): (local max, local expsum)
__device__ float  g_qkvt[BC_][6][T_];      // qt0,qt1,kt0,kt1,vt0,vt1
__device__ float  g_cnp [BC_][4][4];       // Cn partials per chunk
__device__ float  g_sqt [B_][32][T_];      // SCALE*sqrt(qt'+eps)
__device__ float  g_A   [B_][2][32][16];   // [b][{s,t}][cd][c']

// ---------------- helpers ----------------
__device__ __forceinline__ float warpSumAll(float v) {
#pragma unroll
    for (int o = 16; o > 0; o >>= 1) v += __shfl_xor_sync(0xffffffffu, v, o);
    return v;
}
__device__ __forceinline__ float warpMaxAll(float v) {
#pragma unroll
    for (int o = 16; o > 0; o >>= 1) v = fmaxf(v, __shfl_xor_sync(0xffffffffu, v, o));
    return v;
}
__device__ __forceinline__ float blockSum256(float v) {
    __shared__ float red[8];
    int lane = threadIdx.x & 31, wid = threadIdx.x >> 5;
    float s = warpSumAll(v);
    __syncthreads();
    if (lane == 0) red[wid] = s;
    __syncthreads();
    float r = red[0];
#pragma unroll
    for (int w = 1; w < 8; w++) r += red[w];
    return r;
}
__device__ __forceinline__ float blockMax256(float v) {
    __shared__ float redm[8];
    int lane = threadIdx.x & 31, wid = threadIdx.x >> 5;
    float s = warpMaxAll(v);
    __syncthreads();
    if (lane == 0) redm[wid] = s;
    __syncthreads();
    float r = redm[0];
#pragma unroll
    for (int w = 1; w < 8; w++) r = fmaxf(r, redm[w]);
    return r;
}
__device__ __forceinline__ unsigned long long pack2(float lo, float hi) {
    unsigned long long r;
    asm("mov.b64 %0, {%1, %2};" : "=l"(r) : "f"(lo), "f"(hi));
    return r;
}
__device__ __forceinline__ unsigned long long fma2(unsigned long long a,
                                                   unsigned long long b,
                                                   unsigned long long c) {
    unsigned long long d;
    asm("fma.rn.f32x2 %0, %1, %2, %3;" : "=l"(d) : "l"(a), "l"(b), "l"(c));
    return d;
}
__device__ __forceinline__ float2 unpk2(unsigned long long v) {
    float2 f;
    asm("mov.b64 {%0, %1}, %2;" : "=f"(f.x), "=f"(f.y) : "l"(v));
    return f;
}
__device__ __forceinline__ float sqrt_ap(float x) {
    float r; asm("sqrt.approx.f32 %0, %1;" : "=f"(r) : "f"(x)); return r;
}
__device__ __forceinline__ float rcp_ap(float x) {
    float r; asm("rcp.approx.f32 %0, %1;" : "=f"(r) : "f"(x)); return r;
}

// ---------------- K1 (fused): z=0 -> spatial proj + S + ks stats; z=1 -> temporal proj ----------------
__global__ __launch_bounds__(256) void k1(const float* __restrict__ x,
                                          const float* __restrict__ wqs,
                                          const float* __restrict__ wqt) {
    int bc = blockIdx.x;
    int j  = threadIdx.x;

    if (blockIdx.z == 0) {
        // ---- spatial: qkv_s over n-chunk of 1024, all t ----
        int chunk = blockIdx.y;
        int n0 = chunk * 1024 + j * 4;
        __shared__ unsigned long long ws2[192];
        if (j < 192) { float w = wqs[j]; ws2[j] = pack2(w, w); }
        __syncthreads();

        const float* xs = x + (size_t)bc * T_ * HW_;
        unsigned long long acc[6][2];
#pragma unroll
        for (int k = 0; k < 6; k++) { acc[k][0] = 0ull; acc[k][1] = 0ull; }

#pragma unroll 4
        for (int t = 0; t < T_; t++) {
            float4 xv = *(const float4*)&xs[(size_t)t * HW_ + n0];
            unsigned long long p0 = pack2(xv.x, xv.y);
            unsigned long long p1 = pack2(xv.z, xv.w);
#pragma unroll
            for (int k = 0; k < 6; k++) {
                unsigned long long w = ws2[k * 32 + t];
                acc[k][0] = fma2(p0, w, acc[k][0]);
                acc[k][1] = fma2(p1, w, acc[k][1]);
            }
        }

        float col[6][4];
#pragma unroll
        for (int k = 0; k < 6; k++) {
            float2 a = unpk2(acc[k][0]), b2 = unpk2(acc[k][1]);
            col[k][0] = a.x; col[k][1] = a.y; col[k][2] = b2.x; col[k][3] = b2.y;
        }

        int b = bc >> 4, c = bc & 15;
        // S = sqrt(softmax over d of qs + eps)
        float4 s0o, s1o;
        float so0[4], so1[4];
#pragma unroll
        for (int m = 0; m < 4; m++) {
            float q0 = col[0][m], q1 = col[1][m];
            float mx = fmaxf(q0, q1);
            float e0 = __expf(q0 - mx), e1 = __expf(q1 - mx);
            float inv = rcp_ap(e0 + e1);
            so0[m] = sqrt_ap(e0 * inv + EPS_);
            so1[m] = sqrt_ap(e1 * inv + EPS_);
        }
        s0o = make_float4(so0[0], so0[1], so0[2], so0[3]);
        s1o = make_float4(so1[0], so1[1], so1[2], so1[3]);
        *(float4*)&g_S[b][2 * c][n0]     = s0o;
        *(float4*)&g_S[b][2 * c + 1][n0] = s1o;

        // store raw ks, vs
        *(float4*)&g_kv[bc][0][n0] = make_float4(col[2][0], col[2][1], col[2][2], col[2][3]);
        *(float4*)&g_kv[bc][1][n0] = make_float4(col[3][0], col[3][1], col[3][2], col[3][3]);
        *(float4*)&g_kv[bc][2][n0] = make_float4(col[4][0], col[4][1], col[4][2], col[4][3]);
        *(float4*)&g_kv[bc][3][n0] = make_float4(col[5][0], col[5][1], col[5][2], col[5][3]);

        // per-chunk ks stats (local max + local expsum), deterministic
        float lm0 = fmaxf(fmaxf(col[2][0], col[2][1]), fmaxf(col[2][2], col[2][3]));
        float lm1 = fmaxf(fmaxf(col[3][0], col[3][1]), fmaxf(col[3][2], col[3][3]));
        float M0 = blockMax256(lm0);
        float M1 = blockMax256(lm1);
        float ls0 = 0.f, ls1 = 0.f;
#pragma unroll
        for (int m = 0; m < 4; m++) {
            ls0 += __expf(col[2][m] - M0);
            ls1 += __expf(col[3][m] - M1);
        }
        float S0 = blockSum256(ls0);
        float S1 = blockSum256(ls1);
        if (j == 0) {
            g_stat[bc][chunk][0] = make_float2(M0, S0);
            g_stat[bc][chunk][1] = make_float2(M1, S1);
        }
    } else {
        // ---- temporal: qkv_t for 8 t, reduce over all n ----
        int t0 = blockIdx.y * 8;
        const float* xs = x + (size_t)bc * T_ * HW_ + (size_t)t0 * HW_;
        float acc[6][8];
#pragma unroll
        for (int k = 0; k < 6; k++)
#pragma unroll
            for (int tt = 0; tt < 8; tt++) acc[k][tt] = 0.f;

        for (int i = 0; i < 16; i++) {
            int n = i * 256 + j;
            float wv[6];
#pragma unroll
            for (int k = 0; k < 6; k++) wv[k] = wqt[k * HW_ + n];
#pragma unroll
            for (int tt = 0; tt < 8; tt++) {
                float v = xs[(size_t)tt * HW_ + n];
#pragma unroll
                for (int k = 0; k < 6; k++) acc[k][tt] += v * wv[k];
            }
        }

        __shared__ float wpart[8][48];
        int lane = j & 31, wid = j >> 5;
#pragma unroll
        for (int k = 0; k < 6; k++)
#pragma unroll
            for (int tt = 0; tt < 8; tt++) {
                float v = warpSumAll(acc[k][tt]);
                if (lane == 0) wpart[wid][k * 8 + tt] = v;
            }
        __syncthreads();
        if (j < 48) {
            float s = 0.f;
#pragma unroll
            for (int w = 0; w < 8; w++) s += wpart[w][j];
            g_qkvt[bc][j >> 3][t0 + (j & 7)] = s;
        }
    }
}

// ---------------- K2cn: combine ks stats, Cn partials per chunk ----------------
__global__ __launch_bounds__(256) void k2cn() {
    int bc = blockIdx.x, chunk = blockIdx.y, j = threadIdx.x;

    float M0 = -1e30f, M1 = -1e30f;
#pragma unroll
    for (int ch = 0; ch < 4; ch++) {
        M0 = fmaxf(M0, g_stat[bc][ch][0].x);
        M1 = fmaxf(M1, g_stat[bc][ch][1].x);
    }
    float Z0 = 0.f, Z1 = 0.f;
#pragma unroll
    for (int ch = 0; ch < 4; ch++) {
        float2 s0 = g_stat[bc][ch][0], s1 = g_stat[bc][ch][1];
        Z0 += s0.y * __expf(s0.x - M0);
        Z1 += s1.y * __expf(s1.x - M1);
    }
    float iZ0 = rcp_ap(Z0), iZ1 = rcp_ap(Z1);

    int n0 = chunk * 1024 + j * 4;
    float4 k0 = *(const float4*)&g_kv[bc][0][n0];
    float4 k1v = *(const float4*)&g_kv[bc][1][n0];
    float4 v0 = *(const float4*)&g_kv[bc][2][n0];
    float4 v1 = *(const float4*)&g_kv[bc][3][n0];
    float ka[4] = {k0.x, k0.y, k0.z, k0.w};
    float kb[4] = {k1v.x, k1v.y, k1v.z, k1v.w};
    float va[4] = {v0.x, v0.y, v0.z, v0.w};
    float vb[4] = {v1.x, v1.y, v1.z, v1.w};

    float cn00 = 0, cn01 = 0, cn10 = 0, cn11 = 0;
#pragma unroll
    for (int m = 0; m < 4; m++) {
        float p0 = __expf(ka[m] - M0) * iZ0 + EPS_;
        float p1 = __expf(kb[m] - M1) * iZ1 + EPS_;
        cn00 += sqrt_ap(p0 * va[m]); cn01 += sqrt_ap(p0 * vb[m]);
        cn10 += sqrt_ap(p1 * va[m]); cn11 += sqrt_ap(p1 * vb[m]);
    }
    cn00 = blockSum256(cn00); cn01 = blockSum256(cn01);
    cn10 = blockSum256(cn10); cn11 = blockSum256(cn11);
    if (j == 0) {
        g_cnp[bc][chunk][0] = cn00; g_cnp[bc][chunk][1] = cn01;
        g_cnp[bc][chunk][2] = cn10; g_cnp[bc][chunk][3] = cn11;
    }
}

// ---------------- K2fin: t-side softmaxes, sqt, ctx, A ----------------
__global__ __launch_bounds__(64) void k2fin(const float* __restrict__ wos,
                                            const float* __restrict__ wot) {
    int bc = blockIdx.x;
    int b = bc >> 4, c = bc & 15;
    int tid = threadIdx.x;
    __shared__ float ctx_sh[4];

    if (tid < 32) {
        int t = tid;
        float q0 = g_qkvt[bc][0][t], q1 = g_qkvt[bc][1][t];
        float mx = fmaxf(q0, q1);
        float e0 = __expf(q0 - mx), e1 = __expf(q1 - mx);
        float inv = rcp_ap(e0 + e1);
        g_sqt[b][2 * c][t]     = SCALE_ * sqrt_ap(e0 * inv + EPS_);
        g_sqt[b][2 * c + 1][t] = SCALE_ * sqrt_ap(e1 * inv + EPS_);

        float k0 = g_qkvt[bc][2][t], k1v = g_qkvt[bc][3][t];
        float M0 = warpMaxAll(k0), M1 = warpMaxAll(k1v);
        float x0 = __expf(k0 - M0), x1 = __expf(k1v - M1);
        float Zi0 = rcp_ap(warpSumAll(x0)), Zi1 = rcp_ap(warpSumAll(x1));
        float kt0 = x0 * Zi0 + EPS_, kt1 = x1 * Zi1 + EPS_;
        float vt0 = g_qkvt[bc][4][t], vt1 = g_qkvt[bc][5][t];
        float c00 = warpSumAll(sqrt_ap(kt0 * vt0));
        float c01 = warpSumAll(sqrt_ap(kt0 * vt1));
        float c10 = warpSumAll(sqrt_ap(kt1 * vt0));
        float c11 = warpSumAll(sqrt_ap(kt1 * vt1));
        if (t == 0) {
            float cn0 = g_cnp[bc][0][0] + g_cnp[bc][1][0] + g_cnp[bc][2][0] + g_cnp[bc][3][0];
            float cn1 = g_cnp[bc][0][1] + g_cnp[bc][1][1] + g_cnp[bc][2][1] + g_cnp[bc][3][1];
            float cn2 = g_cnp[bc][0][2] + g_cnp[bc][1][2] + g_cnp[bc][2][2] + g_cnp[bc][3][2];
            float cn3 = g_cnp[bc][0][3] + g_cnp[bc][1][3] + g_cnp[bc][2][3] + g_cnp[bc][3][3];
            ctx_sh[0] = SCALE_ * c00 * cn0;
            ctx_sh[1] = SCALE_ * c01 * cn1;
            ctx_sh[2] = SCALE_ * c10 * cn2;
            ctx_sh[3] = SCALE_ * c11 * cn3;
        }
    }
    __syncthreads();

    int st = tid >> 5, d = (tid >> 4) & 1, cp = tid & 15;
    const float* w = st ? wot : wos;
    float x0 = ctx_sh[2 * d], x1 = ctx_sh[2 * d + 1];
    g_A[b][st][2 * c + d][cp] = w[cp * 32 + 2 * c] * x0 + w[cp * 32 + 2 * c + 1] * x1;
}

// ---------------- K3: out[c',t,n] = sqrt( (Gs.S)*(Gt.S) ), G = A * sqt[t] ----------------
// grid (32 ntiles of 128, 4 b, 2 tchunks of 16). 256 threads = (tp2, cg4, ng32).
// f32x2 packed over n; G stored pre-duplicated (g,g) in smem.
__global__ __launch_bounds__(256, 3) void k3(float* __restrict__ out) {
    int nt = blockIdx.x, b = blockIdx.y, tc = blockIdx.z;
    int n0 = nt * 128;
    int j = threadIdx.x;

    __shared__ float Ssh[32][128];                         // 16 KB
    __shared__ float sqt_sh[32][16];                       // 2 KB
    __shared__ unsigned long long Gsh[2][2][32][16];       // 16 KB (dup pairs)

    float4 myA = ((const float4*)&g_A[b][0][0][0])[j];
    int stA = j >> 7, cdA = (j >> 2) & 31, cpA = (j & 3) * 4;

#pragma unroll
    for (int u = 0; u < 4; u++) {
        int idx = u * 256 + j;
        int r = idx >> 5, q = idx & 31;
        ((float4*)&Ssh[r][0])[q] = ((const float4*)&g_S[b][r][n0])[q];
    }
#pragma unroll
    for (int u = 0; u < 2; u++) {
        int idx = u * 256 + j;
        int cd = idx >> 4, q = idx & 15;
        sqt_sh[cd][q] = g_sqt[b][cd][tc * 16 + q];
    }
    __syncthreads();

    int tp = j >> 7, cg = (j >> 5) & 3, ng = j & 31;
    int cpb = cg * 4;

    for (int i = 0; i < 8; i++) {
        // build G (duplicated pairs) for the two t of this pass
#pragma unroll
        for (int p = 0; p < 2; p++) {
            float sq = sqt_sh[cdA][2 * i + p];
            float v0 = myA.x * sq, v1 = myA.y * sq, v2 = myA.z * sq, v3 = myA.w * sq;
            ulonglong2 w0, w1;
            w0.x = pack2(v0, v0); w0.y = pack2(v1, v1);
            w1.x = pack2(v2, v2); w1.y = pack2(v3, v3);
            *(ulonglong2*)&Gsh[p][stA][cdA][cpA]     = w0;
            *(ulonglong2*)&Gsh[p][stA][cdA][cpA + 2] = w1;
        }
        __syncthreads();

        unsigned long long aS[4][2], aT[4][2];
#pragma unroll
        for (int p = 0; p < 4; p++) { aS[p][0] = 0ull; aS[p][1] = 0ull; aT[p][0] = 0ull; aT[p][1] = 0ull; }

#pragma unroll 4
        for (int cd = 0; cd < 32; cd++) {
            ulonglong2 sp  = *(const ulonglong2*)&Ssh[cd][ng * 4];
            ulonglong2 gsa = *(const ulonglong2*)&Gsh[tp][0][cd][cpb];
            ulonglong2 gsb = *(const ulonglong2*)&Gsh[tp][0][cd][cpb + 2];
            ulonglong2 gta = *(const ulonglong2*)&Gsh[tp][1][cd][cpb];
            ulonglong2 gtb = *(const ulonglong2*)&Gsh[tp][1][cd][cpb + 2];
            aS[0][0] = fma2(gsa.x, sp.x, aS[0][0]); aS[0][1] = fma2(gsa.x, sp.y, aS[0][1]);
            aS[1][0] = fma2(gsa.y, sp.x, aS[1][0]); aS[1][1] = fma2(gsa.y, sp.y, aS[1][1]);
            aS[2][0] = fma2(gsb.x, sp.x, aS[2][0]); aS[2][1] = fma2(gsb.x, sp.y, aS[2][1]);
            aS[3][0] = fma2(gsb.y, sp.x, aS[3][0]); aS[3][1] = fma2(gsb.y, sp.y, aS[3][1]);
            aT[0][0] = fma2(gta.x, sp.x, aT[0][0]); aT[0][1] = fma2(gta.x, sp.y, aT[0][1]);
            aT[1][0] = fma2(gta.y, sp.x, aT[1][0]); aT[1][1] = fma2(gta.y, sp.y, aT[1][1]);
            aT[2][0] = fma2(gtb.x, sp.x, aT[2][0]); aT[2][1] = fma2(gtb.x, sp.y, aT[2][1]);
            aT[3][0] = fma2(gtb.y, sp.x, aT[3][0]); aT[3][1] = fma2(gtb.y, sp.y, aT[3][1]);
        }

        int t = tc * 16 + 2 * i + tp;
#pragma unroll
        for (int p = 0; p < 4; p++) {
            float2 sa = unpk2(aS[p][0]), sb = unpk2(aS[p][1]);
            float2 ta = unpk2(aT[p][0]), tb = unpk2(aT[p][1]);
            float4 o;
            o.x = sqrt_ap(sa.x * ta.x); o.y = sqrt_ap(sa.y * ta.y);
            o.z = sqrt_ap(sb.x * tb.x); o.w = sqrt_ap(sb.y * tb.y);
            *(float4*)&out[(((size_t)(b * 16 + cpb + p) * T_ + t) * HW_) + n0 + ng * 4] = o;
        }
        __syncthreads();
    }
}

// ---------------- launch ----------------
extern "C" void kernel_launch(void* const* d_in, const int* in_sizes, int n_in,
                              void* d_out, int out_size) {
    const float* x   = (const float*)d_in[0];
    const float* wqs = (const float*)d_in[1];
    const float* wqt = (const float*)d_in[2];
    const float* wos = (const float*)d_in[3];
    const float* wot = (const float*)d_in[4];
    float* out = (float*)d_out;

    k1   <<<dim3(BC_, 4, 2), 256>>>(x, wqs, wqt);
    k2cn <<<dim3(BC_, 4), 256>>>();
    k2fin<<<BC_, 64>>>(wos, wot);
    k3   <<<dim3(32, B_, 2), 256>>>(out);
}

// round 4
// speedup vs baseline: 1.7180x; 1.0679x over previous
#include <cuda_runtime.h>
#include <math.h>

#define B_   4
#define C_   16
#define T_   32
#define HW_  4096
#define BC_  64
#define EPS_ 1e-10f
#define SCALE_ 0.8408964152537145f   // 2^-0.25

typedef unsigned long long u64;

// ---------------- scratch (device globals) ----------------
__device__ float  g_S   [B_][32][HW_];     // sqrt(softmax_d(qs)+eps)
__device__ float  g_qkvt[BC_][6][T_];      // qt0,qt1,kt0,kt1,vt0,vt1
__device__ float  g_zp  [BC_][4][2];       // per-chunk expsum partials of ks
__device__ float  g_cnp [BC_][4][4];       // per-chunk Cn partials (no 1/sqrt(Z))
__device__ float  g_sqt [B_][32][T_];      // SCALE*sqrt(qt'+eps)
__device__ float  g_A   [B_][2][32][16];   // [b][{s,t}][cd][c']

// ---------------- helpers ----------------
__device__ __forceinline__ float warpSumAll(float v) {
#pragma unroll
    for (int o = 16; o > 0; o >>= 1) v += __shfl_xor_sync(0xffffffffu, v, o);
    return v;
}
__device__ __forceinline__ float warpMaxAll(float v) {
#pragma unroll
    for (int o = 16; o > 0; o >>= 1) v = fmaxf(v, __shfl_xor_sync(0xffffffffu, v, o));
    return v;
}
__device__ __forceinline__ float blockSum256(float v) {
    __shared__ float red[8];
    int lane = threadIdx.x & 31, wid = threadIdx.x >> 5;
    float s = warpSumAll(v);
    __syncthreads();
    if (lane == 0) red[wid] = s;
    __syncthreads();
    float r = red[0];
#pragma unroll
    for (int w = 1; w < 8; w++) r += red[w];
    return r;
}
__device__ __forceinline__ u64 pack2(float lo, float hi) {
    u64 r; asm("mov.b64 %0, {%1, %2};" : "=l"(r) : "f"(lo), "f"(hi)); return r;
}
__device__ __forceinline__ u64 fma2(u64 a, u64 b, u64 c) {
    u64 d; asm("fma.rn.f32x2 %0, %1, %2, %3;" : "=l"(d) : "l"(a), "l"(b), "l"(c)); return d;
}
__device__ __forceinline__ u64 mul2(u64 a, u64 b) {
    u64 d; asm("mul.rn.f32x2 %0, %1, %2;" : "=l"(d) : "l"(a), "l"(b)); return d;
}
__device__ __forceinline__ float2 unpk2(u64 v) {
    float2 f; asm("mov.b64 {%0, %1}, %2;" : "=f"(f.x), "=f"(f.y) : "l"(v)); return f;
}
__device__ __forceinline__ float sqrt_ap(float x) {
    float r; asm("sqrt.approx.f32 %0, %1;" : "=f"(r) : "f"(x)); return r;
}
__device__ __forceinline__ float rcp_ap(float x) {
    float r; asm("rcp.approx.f32 %0, %1;" : "=f"(r) : "f"(x)); return r;
}
__device__ __forceinline__ float rsqrt_ap(float x) {
    float r; asm("rsqrt.approx.f32 %0, %1;" : "=f"(r) : "f"(x)); return r;
}

// ---------------- K1 (fused): z=0 spatial proj + S + stats; z=1 temporal proj ----------------
__global__ __launch_bounds__(256) void k1(const float* __restrict__ x,
                                          const float* __restrict__ wqs,
                                          const float* __restrict__ wqt) {
    int bc = blockIdx.x;
    int j  = threadIdx.x;

    if (blockIdx.z == 0) {
        int chunk = blockIdx.y;
        int n0 = chunk * 1024 + j * 4;
        __shared__ u64 ws2[192];
        if (j < 192) { float w = wqs[j]; ws2[j] = pack2(w, w); }
        __syncthreads();

        const float* xs = x + (size_t)bc * T_ * HW_;
        u64 acc[6][2];
#pragma unroll
        for (int k = 0; k < 6; k++) { acc[k][0] = 0ull; acc[k][1] = 0ull; }

#pragma unroll 4
        for (int t = 0; t < T_; t++) {
            float4 xv = *(const float4*)&xs[(size_t)t * HW_ + n0];
            u64 p0 = pack2(xv.x, xv.y);
            u64 p1 = pack2(xv.z, xv.w);
#pragma unroll
            for (int k = 0; k < 6; k++) {
                u64 w = ws2[k * 32 + t];
                acc[k][0] = fma2(p0, w, acc[k][0]);
                acc[k][1] = fma2(p1, w, acc[k][1]);
            }
        }

        float col[6][4];
#pragma unroll
        for (int k = 0; k < 6; k++) {
            float2 a = unpk2(acc[k][0]), b2 = unpk2(acc[k][1]);
            col[k][0] = a.x; col[k][1] = a.y; col[k][2] = b2.x; col[k][3] = b2.y;
        }

        int b = bc >> 4, c = bc & 15;
        // S = sqrt(softmax over d of qs + eps)
        float so0[4], so1[4];
#pragma unroll
        for (int m = 0; m < 4; m++) {
            float q0 = col[0][m], q1 = col[1][m];
            float mx = fmaxf(q0, q1);
            float e0 = __expf(q0 - mx), e1 = __expf(q1 - mx);
            float inv = rcp_ap(e0 + e1);
            so0[m] = sqrt_ap(e0 * inv + EPS_);
            so1[m] = sqrt_ap(e1 * inv + EPS_);
        }
        *(float4*)&g_S[b][2 * c][n0]     = make_float4(so0[0], so0[1], so0[2], so0[3]);
        *(float4*)&g_S[b][2 * c + 1][n0] = make_float4(so1[0], so1[1], so1[2], so1[3]);

        // ks stats + Cn partials (no max subtraction: ks in [0,~2])
        float z0 = 0.f, z1 = 0.f;
        float cn00 = 0, cn01 = 0, cn10 = 0, cn11 = 0;
#pragma unroll
        for (int m = 0; m < 4; m++) {
            float e0 = __expf(col[2][m]);
            float e1 = __expf(col[3][m]);
            z0 += e0; z1 += e1;
            float va = col[4][m], vb = col[5][m];
            cn00 += sqrt_ap(e0 * va); cn01 += sqrt_ap(e0 * vb);
            cn10 += sqrt_ap(e1 * va); cn11 += sqrt_ap(e1 * vb);
        }
        z0   = blockSum256(z0);   z1   = blockSum256(z1);
        cn00 = blockSum256(cn00); cn01 = blockSum256(cn01);
        cn10 = blockSum256(cn10); cn11 = blockSum256(cn11);
        if (j == 0) {
            g_zp[bc][chunk][0] = z0; g_zp[bc][chunk][1] = z1;
            g_cnp[bc][chunk][0] = cn00; g_cnp[bc][chunk][1] = cn01;
            g_cnp[bc][chunk][2] = cn10; g_cnp[bc][chunk][3] = cn11;
        }
    } else {
        // temporal: qkv_t for 8 t, reduce over all n
        int t0 = blockIdx.y * 8;
        const float* xs = x + (size_t)bc * T_ * HW_ + (size_t)t0 * HW_;
        float acc[6][8];
#pragma unroll
        for (int k = 0; k < 6; k++)
#pragma unroll
            for (int tt = 0; tt < 8; tt++) acc[k][tt] = 0.f;

        for (int i = 0; i < 16; i++) {
            int n = i * 256 + j;
            float wv[6];
#pragma unroll
            for (int k = 0; k < 6; k++) wv[k] = wqt[k * HW_ + n];
#pragma unroll
            for (int tt = 0; tt < 8; tt++) {
                float v = xs[(size_t)tt * HW_ + n];
#pragma unroll
                for (int k = 0; k < 6; k++) acc[k][tt] += v * wv[k];
            }
        }

        __shared__ float wpart[8][48];
        int lane = j & 31, wid = j >> 5;
#pragma unroll
        for (int k = 0; k < 6; k++)
#pragma unroll
            for (int tt = 0; tt < 8; tt++) {
                float v = warpSumAll(acc[k][tt]);
                if (lane == 0) wpart[wid][k * 8 + tt] = v;
            }
        __syncthreads();
        if (j < 48) {
            float s = 0.f;
#pragma unroll
            for (int w = 0; w < 8; w++) s += wpart[w][j];
            g_qkvt[bc][j >> 3][t0 + (j & 7)] = s;
        }
    }
}

// ---------------- K2fin: t-side softmaxes, sqt, ctx, A ----------------
__global__ __launch_bounds__(64) void k2fin(const float* __restrict__ wos,
                                            const float* __restrict__ wot) {
    int bc = blockIdx.x;
    int b = bc >> 4, c = bc & 15;
    int tid = threadIdx.x;
    __shared__ float ctx_sh[4];

    if (tid < 32) {
        int t = tid;
        float q0 = g_qkvt[bc][0][t], q1 = g_qkvt[bc][1][t];
        float mx = fmaxf(q0, q1);
        float e0 = __expf(q0 - mx), e1 = __expf(q1 - mx);
        float inv = rcp_ap(e0 + e1);
        g_sqt[b][2 * c][t]     = SCALE_ * sqrt_ap(e0 * inv + EPS_);
        g_sqt[b][2 * c + 1][t] = SCALE_ * sqrt_ap(e1 * inv + EPS_);

        float k0 = g_qkvt[bc][2][t], k1v = g_qkvt[bc][3][t];
        float M0 = warpMaxAll(k0), M1 = warpMaxAll(k1v);
        float x0 = __expf(k0 - M0), x1 = __expf(k1v - M1);
        float Zi0 = rcp_ap(warpSumAll(x0)), Zi1 = rcp_ap(warpSumAll(x1));
        float kt0 = x0 * Zi0 + EPS_, kt1 = x1 * Zi1 + EPS_;
        float vt0 = g_qkvt[bc][4][t], vt1 = g_qkvt[bc][5][t];
        float c00 = warpSumAll(sqrt_ap(kt0 * vt0));
        float c01 = warpSumAll(sqrt_ap(kt0 * vt1));
        float c10 = warpSumAll(sqrt_ap(kt1 * vt0));
        float c11 = warpSumAll(sqrt_ap(kt1 * vt1));
        if (t == 0) {
            float Z0 = 0.f, Z1 = 0.f, cns[4] = {0.f, 0.f, 0.f, 0.f};
#pragma unroll
            for (int ch = 0; ch < 4; ch++) {
                Z0 += g_zp[bc][ch][0];
                Z1 += g_zp[bc][ch][1];
#pragma unroll
                for (int i = 0; i < 4; i++) cns[i] += g_cnp[bc][ch][i];
            }
            float r0 = rsqrt_ap(Z0), r1 = rsqrt_ap(Z1);
            ctx_sh[0] = SCALE_ * c00 * cns[0] * r0;
            ctx_sh[1] = SCALE_ * c01 * cns[1] * r0;
            ctx_sh[2] = SCALE_ * c10 * cns[2] * r1;
            ctx_sh[3] = SCALE_ * c11 * cns[3] * r1;
        }
    }
    __syncthreads();

    int st = tid >> 5, d = (tid >> 4) & 1, cp = tid & 15;
    const float* w = st ? wot : wos;
    float x0 = ctx_sh[2 * d], x1 = ctx_sh[2 * d + 1];
    g_A[b][st][2 * c + d][cp] = w[cp * 32 + 2 * c] * x0 + w[cp * 32 + 2 * c + 1] * x1;
}

// ---------------- K3: out[c',t,n] = sqrt( (Gs.S)*(Gt.S) ), G = A * sqt[t] ----------------
// grid (32 ntiles of 128 n, 4 b, 2 tchunks of 16 t). 256 threads = (cg 8, ng 32).
// Thread tile: 2 c' x 8 n (4 u64) x 4 t, both branches. t amortized in registers:
// per cd: m[tt][np] = S*sqt, acc += A*m. A & sqt dup-packed in smem; no mainloop syncs.
__global__ __launch_bounds__(256, 2) void k3(float* __restrict__ out) {
    int nt = blockIdx.x, b = blockIdx.y, tc = blockIdx.z;
    int n0 = nt * 128;
    int j = threadIdx.x;

    __shared__ u64 S2[32][64];      // 16 KB : S pairs along n
    __shared__ u64 Ad[32][8][4];    // 8 KB  : [cd][cg]{As0,As1,At0,At1} dup
    __shared__ u64 qd[32][16];      // 4 KB  : dup sqt for this tchunk

    // S: just alias float4 -> two consecutive-n u64s (memory order matches f32x2 lo/hi)
#pragma unroll
    for (int u = 0; u < 4; u++) {
        int idx = u * 256 + j;
        int r = idx >> 5, q = idx & 31;
        *(float4*)&S2[r][q * 2] = ((const float4*)&g_S[b][r][n0])[q];
    }
    // Ad: thread j -> (cd = j>>3, cg = j&7)
    {
        int cd = j >> 3, cg = j & 7;
        float s0 = g_A[b][0][cd][cg * 2], s1 = g_A[b][0][cd][cg * 2 + 1];
        float t0 = g_A[b][1][cd][cg * 2], t1 = g_A[b][1][cd][cg * 2 + 1];
        Ad[cd][cg][0] = pack2(s0, s0); Ad[cd][cg][1] = pack2(s1, s1);
        Ad[cd][cg][2] = pack2(t0, t0); Ad[cd][cg][3] = pack2(t1, t1);
    }
    // qd: thread j -> cd = j>>3, two t entries
    {
        int cd = j >> 3, t2 = (j & 7) * 2;
        float a = g_sqt[b][cd][tc * 16 + t2];
        float bb = g_sqt[b][cd][tc * 16 + t2 + 1];
        qd[cd][t2]     = pack2(a, a);
        qd[cd][t2 + 1] = pack2(bb, bb);
    }
    __syncthreads();

    int cg = j >> 5, ng = j & 31;

    for (int pp = 0; pp < 4; pp++) {
        u64 acc[2][2][4][2];    // [st][pc][tt][np]
#pragma unroll
        for (int a = 0; a < 2; a++)
#pragma unroll
            for (int p = 0; p < 2; p++)
#pragma unroll
                for (int tt = 0; tt < 4; tt++) { acc[a][p][tt][0] = 0ull; acc[a][p][tt][1] = 0ull; }

#pragma unroll 4
        for (int cd = 0; cd < 32; cd++) {
            ulonglong2 sp  = *(const ulonglong2*)&S2[cd][ng * 2];       // per-lane, 4 n
            ulonglong2 avs = *(const ulonglong2*)&Ad[cd][cg][0];        // broadcast As
            ulonglong2 avt = *(const ulonglong2*)&Ad[cd][cg][2];        // broadcast At
            ulonglong2 q01 = *(const ulonglong2*)&qd[cd][pp * 4];       // broadcast q0,q1
            ulonglong2 q23 = *(const ulonglong2*)&qd[cd][pp * 4 + 2];   // broadcast q2,q3
            u64 qv[4] = {q01.x, q01.y, q23.x, q23.y};
#pragma unroll
            for (int tt = 0; tt < 4; tt++) {
                u64 m0 = mul2(sp.x, qv[tt]);
                u64 m1 = mul2(sp.y, qv[tt]);
                acc[0][0][tt][0] = fma2(avs.x, m0, acc[0][0][tt][0]);
                acc[0][0][tt][1] = fma2(avs.x, m1, acc[0][0][tt][1]);
                acc[0][1][tt][0] = fma2(avs.y, m0, acc[0][1][tt][0]);
                acc[0][1][tt][1] = fma2(avs.y, m1, acc[0][1][tt][1]);
                acc[1][0][tt][0] = fma2(avt.x, m0, acc[1][0][tt][0]);
                acc[1][0][tt][1] = fma2(avt.x, m1, acc[1][0][tt][1]);
                acc[1][1][tt][0] = fma2(avt.y, m0, acc[1][1][tt][0]);
                acc[1][1][tt][1] = fma2(avt.y, m1, acc[1][1][tt][1]);
            }
        }

        int tbase = tc * 16 + pp * 4;
#pragma unroll
        for (int pc = 0; pc < 2; pc++) {
            int cp = cg * 2 + pc;
#pragma unroll
            for (int tt = 0; tt < 4; tt++) {
                float2 s0 = unpk2(acc[0][pc][tt][0]), s1 = unpk2(acc[0][pc][tt][1]);
                float2 t0 = unpk2(acc[1][pc][tt][0]), t1 = unpk2(acc[1][pc][tt][1]);
                float4 o;
                o.x = sqrt_ap(s0.x * t0.x); o.y = sqrt_ap(s0.y * t0.y);
                o.z = sqrt_ap(s1.x * t1.x); o.w = sqrt_ap(s1.y * t1.y);
                *(float4*)&out[(((size_t)(b * 16 + cp) * T_ + tbase + tt) * HW_) + n0 + ng * 4] = o;
            }
        }
    }
}

// ---------------- launch ----------------
extern "C" void kernel_launch(void* const* d_in, const int* in_sizes, int n_in,
                              void* d_out, int out_size) {
    const float* x   = (const float*)d_in[0];
    const float* wqs = (const float*)d_in[1];
    const float* wqt = (const float*)d_in[2];
    const float* wos = (const float*)d_in[3];
    const float* wot = (const float*)d_in[4];
    float* out = (float*)d_out;

    k1   <<<dim3(BC_, 4, 2), 256>>>(x, wqs, wqt);
    k2fin<<<BC_, 64>>>(wos, wot);
    k3   <<<dim3(32, B_, 2), 256>>>(out);
}